// round 10
// baseline (speedup 1.0000x reference)
#include <cuda_runtime.h>
#include <math.h>
#include <stdint.h>

#define NB   2
#define L    2048
#define H    8
#define D    64
#define HD   512
#define LHD  1048576
#define P    16
#define C    64
#define NC   32
#define EPSF 1e-6f
#define SDT  68      // padded stride (floats), 16B-aligned rows

// ---------------- scratch ----------------
__device__ float g_sq[P*L*D];      // sigmoid(q); overwritten with q_scaled
__device__ float g_sk[P*L*D];
__device__ float g_ST[P*NC*C*C];   // g_ST[j*64+l] = S[l][j]
__device__ float g_ksum[P*NC*D];
__device__ float g_qsum[P*NC*D];
__device__ float g_kso[P*NC*D];
__device__ float g_qsi[P*NC*D];
__device__ float g_si[P*L];
__device__ float g_so[P*L];
__device__ float g_rk[P*L];
__device__ float g_rq[P*L];
__device__ float g_sa[P*L];
__device__ float g_es[P*L];
__device__ float g_comp[P*L];      // source_competition factor
__device__ float g_essum[P*NC];
__device__ float g_kvc[P*NC*D*D];

typedef unsigned long long ull;
__device__ __forceinline__ ull pack2(float a, float b){
  ull r; asm("mov.b64 %0, {%1,%2};" : "=l"(r) : "f"(a), "f"(b)); return r;
}
__device__ __forceinline__ void fma2(ull &acc, ull a, ull b){
  asm("fma.rn.f32x2 %0, %1, %2, %0;" : "+l"(acc) : "l"(a), "l"(b));
}
__device__ __forceinline__ ull mul2(ull a, ull b){
  ull r; asm("mul.rn.f32x2 %0, %1, %2;" : "=l"(r) : "l"(a), "l"(b)); return r;
}
__device__ __forceinline__ float2 unpack2(ull v){
  float2 r; asm("mov.b64 {%0,%1}, %2;" : "=f"(r.x), "=f"(r.y) : "l"(v)); return r;
}
__device__ __forceinline__ float sigmoidf_(float x){ return 1.f/(1.f+__expf(-x)); }
__device__ __forceinline__ float f4get(const float4& v, int u){
  return (u==0)?v.x:(u==1)?v.y:(u==2)?v.z:v.w;
}
__device__ __forceinline__ float red4(float v){
  v += __shfl_xor_sync(0xffffffffu, v, 1);
  v += __shfl_xor_sync(0xffffffffu, v, 2);
  return v;
}

// ---------------- K1: sigmoid + chunk sums (256 thr) ----------------
__global__ void __launch_bounds__(256) k_prep(const float* __restrict__ Q, const float* __restrict__ K){
  __shared__ float2 ps[256];
  int c = blockIdx.x, p = blockIdx.y;
  int t = threadIdx.x, d = t&63, g = t>>6;
  const float* Qp = Q + (size_t)(p>>3)*LHD + (size_t)(p&7)*D + d;
  const float* Kp = K + (size_t)(p>>3)*LHD + (size_t)(p&7)*D + d;
  int l0 = c*C;
  int ob = (p*L + l0)*D + d;
  float ks=0.f, qs=0.f;
  #pragma unroll 4
  for(int j=g; j<C; j+=4){
    float qv = sigmoidf_(Qp[(size_t)(l0+j)*HD]);
    float kv = sigmoidf_(Kp[(size_t)(l0+j)*HD]);
    g_sq[ob + j*D] = qv;
    g_sk[ob + j*D] = kv;
    qs += qv; ks += kv;
  }
  ps[t] = make_float2(ks, qs);
  __syncthreads();
  if(t < 64){
    float2 a=ps[t], b=ps[t+64], cc=ps[t+128], dd=ps[t+192];
    g_ksum[(p*NC+c)*D+t] = a.x+b.x+cc.x+dd.x;
    g_qsum[(p*NC+c)*D+t] = a.y+b.y+cc.y+dd.y;
  }
}

// ---------------- K2: gram + si/so (256 thr, pipelined 4x4 tiles) ----------------
__global__ void __launch_bounds__(256) k_siso(){
  extern __shared__ float sm[];
  float* sqs = sm;                 // [l][d] stride 68
  float* skT = sm + C*SDT;         // [d][j] stride 68
  float* Ssm = sm + 2*C*SDT;       // [l][j] stride 68
  __shared__ float rsk[C], rsq[C], b1s[C], b2s[C], sis[C], sos[C], kpre[D], qpre[D];
  __shared__ float2 ps2[256];
  int c=blockIdx.x, p=blockIdx.y, t=threadIdx.x;
  int base = (p*L + c*C)*D;
  const float4* gq = (const float4*)(g_sq+base);
  const float4* gk = (const float4*)(g_sk+base);
  #pragma unroll
  for(int i=t;i<1024;i+=256){
    int row = i>>4, col4 = (i&15)*4;
    *(float4*)(sqs + row*SDT + col4) = gq[i];
    float4 k4 = gk[i];
    skT[(col4  )*SDT + row] = k4.x;
    skT[(col4+1)*SDT + row] = k4.y;
    skT[(col4+2)*SDT + row] = k4.z;
    skT[(col4+3)*SDT + row] = k4.w;
  }
  { int d=t&63, g=t>>6; float a=0.f, b=0.f;
    for(int cp=g;cp<c;cp+=4){ a += g_ksum[(p*NC+cp)*D+d]; b += g_qsum[(p*NC+cp)*D+d]; }
    ps2[t] = make_float2(a,b);
  }
  __syncthreads();
  if(t<64){
    kpre[t] = ps2[t].x+ps2[t+64].x+ps2[t+128].x+ps2[t+192].x;
    qpre[t] = ps2[t].y+ps2[t+64].y+ps2[t+128].y+ps2[t+192].y;
  }
  __syncthreads();

  int ls = t>>2, gs = t&3;
  // Section A: per-l dots, 4-way split
  { float rq=0.f, b1=0.f, rk=0.f, b2=0.f;
    #pragma unroll
    for(int u=0;u<4;u++){
      int dd = 16*gs + 4*u;
      float4 q4 = *(const float4*)(sqs + ls*SDT + dd);
      rq += q4.x+q4.y+q4.z+q4.w;
      b1 += (q4.x+EPSF)*(kpre[dd]+EPSF) + (q4.y+EPSF)*(kpre[dd+1]+EPSF)
          + (q4.z+EPSF)*(kpre[dd+2]+EPSF) + (q4.w+EPSF)*(kpre[dd+3]+EPSF);
    }
    #pragma unroll
    for(int u=0;u<16;u++){
      int d = 4*u + gs;
      float kv = skT[d*SDT + ls];
      rk += kv; b2 += (kv+EPSF)*(qpre[d]+EPSF);
    }
    rq = red4(rq); b1 = red4(b1); rk = red4(rk); b2 = red4(b2);
    if(gs==0){ rsq[ls]=rq; b1s[ls]=b1; rsk[ls]=rk; b2s[ls]=b2; }
  }

  // gram: 4l x 4j per thread, double-buffered over 16 dq-groups
  int l0 = 4*(t>>4), j0 = 4*(t&15);
  ull acc[8];
  #pragma unroll
  for(int m=0;m<8;m++) acc[m]=0ull;
  {
    float4 qb[2][4]; double2 kb[2][4];
    #pragma unroll
    for(int u=0;u<4;u++){
      qb[0][u] = *(const float4*)(sqs + (l0+u)*SDT);
      kb[0][u] = *(const double2*)(skT + u*SDT + j0);
    }
    #pragma unroll
    for(int jb=0;jb<16;jb++){
      int cur = jb&1, nxt = cur^1;
      if(jb<15){
        int dq = 4*jb+4;
        #pragma unroll
        for(int u=0;u<4;u++){
          qb[nxt][u] = *(const float4*)(sqs + (l0+u)*SDT + dq);
          kb[nxt][u] = *(const double2*)(skT + (dq+u)*SDT + j0);
        }
      }
      #pragma unroll
      for(int du=0;du<4;du++){
        ull k0=(ull)__double_as_longlong(kb[cur][du].x);
        ull k1=(ull)__double_as_longlong(kb[cur][du].y);
        #pragma unroll
        for(int ll=0;ll<4;ll++){
          float qv = f4get(qb[cur][ll], du);
          ull q2 = pack2(qv,qv);
          fma2(acc[ll*2],   q2, k0);
          fma2(acc[ll*2+1], q2, k1);
        }
      }
    }
  }
  float vals[4][4];
  #pragma unroll
  for(int ll=0;ll<4;ll++){
    float2 a0=unpack2(acc[ll*2]), a1=unpack2(acc[ll*2+1]);
    vals[ll][0]=a0.x; vals[ll][1]=a0.y; vals[ll][2]=a1.x; vals[ll][3]=a1.y;
    *(float4*)(Ssm + (l0+ll)*SDT + j0) = make_float4(a0.x,a0.y,a1.x,a1.y);
  }
  int stbase = (p*NC+c)*C*C;
  #pragma unroll
  for(int jj=0;jj<4;jj++)
    *(float4*)(g_ST + stbase + (j0+jj)*C + l0) =
      make_float4(vals[0][jj], vals[1][jj], vals[2][jj], vals[3][jj]);
  __syncthreads();

  // Section B: causal sums, 4-way split
  { float d1=0.f, d2=0.f;
    for(int i=gs; i<=ls; i+=4){
      d1 += Ssm[ls*SDT+i] + EPSF*rsk[i];
      d2 += Ssm[i*SDT+ls] + EPSF*rsq[i];
    }
    d1 = red4(d1); d2 = red4(d2);
    if(gs==0){
      float dot1 = b1s[ls] + d1, dot2 = b2s[ls] + d2;
      float nrm = (float)(c*C + ls + 1);
      float si = nrm/dot1, so = nrm/dot2;
      sis[ls]=si; sos[ls]=so;
      int gl = p*L + c*C + ls;
      g_si[gl]=si; g_so[gl]=so; g_rk[gl]=rsk[ls]; g_rq[gl]=rsq[ls];
    }
  }
  __syncthreads();

  // Section C: kso/qsi chunk sums, 4-way split
  { float a1=0.f, a2=0.f;
    #pragma unroll
    for(int u=0;u<16;u++){
      int j = 4*u + gs;
      a1 += skT[ls*SDT+j]*sos[j];
      a2 += sqs[j*SDT+ls]*sis[j];
    }
    a1 = red4(a1); a2 = red4(a2);
    if(gs==0){
      g_kso[(p*NC+c)*D+ls] = a1;
      g_qsi[(p*NC+c)*D+ls] = a2;
    }
  }
}

// ---------------- K3: conserved (256 thr, 4-way split) ----------------
__global__ void __launch_bounds__(256) k_conserved(){
  extern __shared__ float sm[];
  float* sqs = sm;               // [l][d] stride 68
  float* sks = sm + C*SDT;       // [l][d] stride 68
  float* STs = sm + 2*C*SDT;     // [j][l] stride 68
  __shared__ float rskv[C], rsqv[C], sis[C], sos[C], kpre[D], qpre[D], facs[C], essh[C];
  __shared__ float2 ps2[256];
  int c=blockIdx.x, p=blockIdx.y, t=threadIdx.x;
  int base = (p*L + c*C)*D;
  int stbase = (p*NC+c)*C*C;
  const float4* gq = (const float4*)(g_sq+base);
  const float4* gk = (const float4*)(g_sk+base);
  const float4* gst = (const float4*)(g_ST+stbase);
  #pragma unroll
  for(int i=t;i<1024;i+=256){
    int row = i>>4, col4 = (i&15)*4;
    *(float4*)(sqs + row*SDT + col4) = gq[i];
    *(float4*)(sks + row*SDT + col4) = gk[i];
    *(float4*)(STs + row*SDT + col4) = gst[i];
  }
  { int d=t&63, g=t>>6; float a=0.f, b=0.f;
    for(int cp=g;cp<c;cp+=4){ a += g_kso[(p*NC+cp)*D+d]; b += g_qsi[(p*NC+cp)*D+d]; }
    ps2[t] = make_float2(a,b);
  }
  if(t<64){
    int gl = p*L + c*C + t;
    rskv[t]=g_rk[gl]; sos[t]=g_so[gl];
  } else if(t<128){
    int l=t-64; int gl = p*L + c*C + l;
    rsqv[l]=g_rq[gl]; sis[l]=g_si[gl];
  }
  __syncthreads();
  if(t<64){
    kpre[t] = ps2[t].x+ps2[t+64].x+ps2[t+128].x+ps2[t+192].x;
    qpre[t] = ps2[t].y+ps2[t+64].y+ps2[t+128].y+ps2[t+192].y;
  }
  __syncthreads();

  int ls = t>>2, gs = t&3;
  { float b3=0.f, b4=0.f;
    #pragma unroll
    for(int u=0;u<4;u++){
      int dd = 16*gs + 4*u;
      float4 q4 = *(const float4*)(sqs + ls*SDT + dd);
      float4 k4 = *(const float4*)(sks + ls*SDT + dd);
      b3 += (q4.x+EPSF)*(kpre[dd]+EPSF) + (q4.y+EPSF)*(kpre[dd+1]+EPSF)
          + (q4.z+EPSF)*(kpre[dd+2]+EPSF) + (q4.w+EPSF)*(kpre[dd+3]+EPSF);
      b4 += (k4.x+EPSF)*(qpre[dd]+EPSF) + (k4.y+EPSF)*(qpre[dd+1]+EPSF)
          + (k4.z+EPSF)*(qpre[dd+2]+EPSF) + (k4.w+EPSF)*(qpre[dd+3]+EPSF);
    }
    for(int i=gs; i<=ls; i+=4){
      b3 += sos[i]*(STs[i*SDT+ls] + EPSF*rskv[i]);
      b4 += sis[i]*(STs[ls*SDT+i] + EPSF*rsqv[i]);
    }
    b3 = red4(b3); b4 = red4(b4);
    if(gs==0){
      float nrm = (float)(c*C + ls + 1);
      float sa = sigmoidf_(b3/nrm);
      float cso = b4/nrm; cso = fminf(1.f, fmaxf(-1.f, cso));
      float es = __expf(cso);
      int gl = p*L + c*C + ls;
      g_sa[gl] = sa; g_es[gl] = es;
      essh[ls]=es;
      facs[ls]=sis[ls]/nrm;
    }
  }
  __syncthreads();
  float4* gqo = (float4*)(g_sq+base);
  #pragma unroll
  for(int i=t;i<1024;i+=256){
    int row = i>>4, col4 = (i&15)*4;
    float4 v = *(const float4*)(sqs + row*SDT + col4);
    float f = facs[row];
    gqo[i] = make_float4(v.x*f, v.y*f, v.z*f, v.w*f);
  }
  if(t<32){
    float v = essh[t] + essh[t+32];
    #pragma unroll
    for(int o=16;o;o>>=1) v += __shfl_down_sync(0xffffffffu, v, o);
    if(t==0) g_essum[p*NC+c] = v;
  }
}

// ---------------- K4: v_scaled + chunk KV (256 thr, pipelined 4x4) ----------------
__global__ void __launch_bounds__(256) k_vkv(const float* __restrict__ V){
  __shared__ __align__(16) float sks[C*D];
  __shared__ __align__(16) float vss[C*D];
  __shared__ float ess[C], comp[C];
  __shared__ float prefsh, wtot0;
  int c=blockIdx.x, p=blockIdx.y, t=threadIdx.x;
  int base = (p*L + c*C)*D;
  const float4* gk = (const float4*)(g_sk+base);
  #pragma unroll
  for(int i=t;i<1024;i+=256) ((float4*)sks)[i] = gk[i];
  if(t<64) ess[t] = g_es[p*L + c*C + t];
  if(t<32){
    float v = (t < c) ? g_essum[p*NC + t] : 0.f;
    #pragma unroll
    for(int o=16;o;o>>=1) v += __shfl_down_sync(0xffffffffu, v, o);
    if(t==0) prefsh = v;
  }
  __syncthreads();
  float xscan = 0.f;
  if(t<64){
    xscan = ess[t];
    #pragma unroll
    for(int o=1;o<32;o<<=1){
      float y = __shfl_up_sync(0xffffffffu, xscan, o);
      if((t&31) >= o) xscan += y;
    }
    if(t==31) wtot0 = xscan;
  }
  __syncthreads();
  if(t<64){
    float cum = prefsh + xscan + ((t>=32)? wtot0 : 0.f);
    float cm = ess[t]/cum * (float)(c*C + t + 1);
    comp[t] = cm;
    g_comp[p*L + c*C + t] = cm;
  }
  __syncthreads();
  const float* Vp = V + (size_t)(p>>3)*LHD + (size_t)(p&7)*D;
  #pragma unroll
  for(int i=t;i<1024;i+=256){
    int j = i>>4, col4 = (i&15)*4;
    float4 v = *(const float4*)(Vp + (size_t)(c*C+j)*HD + col4);
    float f = comp[j];
    ((float4*)vss)[i] = make_float4(v.x*f, v.y*f, v.z*f, v.w*f);
  }
  __syncthreads();
  // KV[d][m] += sk[j][d]*vs[j][m]; double-buffered over 16 j-groups
  int d0 = 4*(t>>4), m0 = 4*(t&15);
  ull acc[8];
  #pragma unroll
  for(int m=0;m<8;m++) acc[m]=0ull;
  {
    float4 skb[2][4]; double2 vb[2][4];
    #pragma unroll
    for(int u=0;u<4;u++){
      skb[0][u] = *(const float4*)(sks + u*D + d0);
      vb[0][u]  = *(const double2*)(vss + u*D + m0);
    }
    #pragma unroll
    for(int jb=0;jb<16;jb++){
      int cur = jb&1, nxt = cur^1;
      if(jb<15){
        int j1 = 4*jb+4;
        #pragma unroll
        for(int u=0;u<4;u++){
          skb[nxt][u] = *(const float4*)(sks + (j1+u)*D + d0);
          vb[nxt][u]  = *(const double2*)(vss + (j1+u)*D + m0);
        }
      }
      #pragma unroll
      for(int u=0;u<4;u++){
        ull v0=(ull)__double_as_longlong(vb[cur][u].x);
        ull v1=(ull)__double_as_longlong(vb[cur][u].y);
        #pragma unroll
        for(int dd=0;dd<4;dd++){
          float a = f4get(skb[cur][u], dd);
          ull a2 = pack2(a,a);
          fma2(acc[dd*2],   a2, v0);
          fma2(acc[dd*2+1], a2, v1);
        }
      }
    }
  }
  size_t kb2 = (size_t)(p*NC+c)*D*D;
  #pragma unroll
  for(int dd=0;dd<4;dd++){
    float2 u0=unpack2(acc[dd*2]), u1=unpack2(acc[dd*2+1]);
    *(float4*)(g_kvc + kb2 + (d0+dd)*D + m0) = make_float4(u0.x,u0.y,u1.x,u1.y);
  }
}

// ---------------- K5: exclusive scan of chunk KV sums ----------------
__global__ void k_scan_kv(){
  int p = blockIdx.y;
  int e4 = blockIdx.x*256 + threadIdx.x;
  size_t stride = (size_t)D*D;
  size_t base = (size_t)p*NC*stride + (size_t)e4*4;
  float4 run = make_float4(0.f,0.f,0.f,0.f);
  #pragma unroll
  for(int c=0;c<NC;c++){
    float4 v = *(const float4*)(g_kvc + base + c*stride);
    *(float4*)(g_kvc + base + c*stride) = run;
    run.x += v.x; run.y += v.y; run.z += v.z; run.w += v.w;
  }
}

// ---------------- K6: causal output (256 thr, pipelined 4x4) ----------------
__global__ void __launch_bounds__(256) k_out(float* __restrict__ OUT, const float* __restrict__ V){
  extern __shared__ float sm[];
  float* qss = sm;             // [l][d] stride 64 (broadcast-only)
  float* STs = sm + C*D;       // [i][l] stride 64 (broadcast-only)
  float* vss = sm + 2*C*D;     // [i][m] stride 64
  float* kvs = sm + 3*C*D;     // [d][m] stride 64
  __shared__ float sa_s[C], fls[C];
  int c=blockIdx.x, p=blockIdx.y, t=threadIdx.x;
  int base = (p*L + c*C)*D;
  size_t kb = (size_t)(p*NC+c)*D*D;
  int stbase = (p*NC+c)*C*C;
  const float4* gq = (const float4*)(g_sq+base);
  const float4* gst = (const float4*)(g_ST+stbase);
  const float4* gkv = (const float4*)(g_kvc+kb);
  const float* Vp = V + (size_t)(p>>3)*LHD + (size_t)(p&7)*D;
  #pragma unroll
  for(int i=t;i<1024;i+=256){
    ((float4*)qss)[i] = gq[i];
    ((float4*)STs)[i] = gst[i];
    ((float4*)kvs)[i] = gkv[i];
    int row = i>>4, col4 = (i&15)*4;
    float cm = g_comp[p*L + c*C + row];
    float4 v = *(const float4*)(Vp + (size_t)(c*C+row)*HD + col4);
    ((float4*)vss)[i] = make_float4(v.x*cm, v.y*cm, v.z*cm, v.w*cm);
  }
  if(t<64){
    int gl = p*L + c*C + t;
    sa_s[t] = g_sa[gl];
    fls[t]  = g_si[gl] / (float)(c*C + t + 1);
  }
  __syncthreads();

  int l0 = 4*(t>>4), m0 = 4*(t&15);
  ull acc[8];
  #pragma unroll
  for(int m=0;m<8;m++) acc[m]=0ull;

  // intra-chunk: full 4-groups (i < l0) unconditional, batched loads
  int nf = l0 >> 2;
  for(int ib=0; ib<nf; ib++){
    float4 st4[4]; double2 va[4];
    #pragma unroll
    for(int u=0;u<4;u++){
      int i = 4*ib+u;
      st4[u] = *(const float4*)(STs + i*D + l0);
      va[u]  = *(const double2*)(vss + i*D + m0);
    }
    #pragma unroll
    for(int u=0;u<4;u++){
      ull v0=(ull)__double_as_longlong(va[u].x), v1=(ull)__double_as_longlong(va[u].y);
      #pragma unroll
      for(int ll=0;ll<4;ll++){
        float s = f4get(st4[u], ll);
        ull s2 = pack2(s,s);
        fma2(acc[ll*2],   s2, v0);
        fma2(acc[ll*2+1], s2, v1);
      }
    }
  }
  // last group i = l0..l0+3 with causal mask
  {
    float4 st4[4]; double2 va[4];
    #pragma unroll
    for(int u=0;u<4;u++){
      int i = l0+u;
      st4[u] = *(const float4*)(STs + i*D + l0);
      va[u]  = *(const double2*)(vss + i*D + m0);
    }
    #pragma unroll
    for(int u=0;u<4;u++){
      ull v0=(ull)__double_as_longlong(va[u].x), v1=(ull)__double_as_longlong(va[u].y);
      #pragma unroll
      for(int ll=0;ll<4;ll++){
        float s = (u <= ll) ? f4get(st4[u], ll) : 0.f;
        ull s2 = pack2(s,s);
        fma2(acc[ll*2],   s2, v0);
        fma2(acc[ll*2+1], s2, v1);
      }
    }
  }
  #pragma unroll
  for(int ll=0;ll<4;ll++){
    float f = fls[l0+ll];
    ull f2 = pack2(f,f);
    acc[ll*2]   = mul2(acc[ll*2],   f2);
    acc[ll*2+1] = mul2(acc[ll*2+1], f2);
  }
  // inter-chunk: double-buffered over 16 dq-groups
  {
    float4 qb[2][4]; double2 kbf[2][4];
    #pragma unroll
    for(int u=0;u<4;u++){
      qb[0][u]  = *(const float4*)(qss + (l0+u)*D);
      kbf[0][u] = *(const double2*)(kvs + u*D + m0);
    }
    #pragma unroll
    for(int jb=0;jb<16;jb++){
      int cur = jb&1, nxt = cur^1;
      if(jb<15){
        int dq = 4*jb+4;
        #pragma unroll
        for(int u=0;u<4;u++){
          qb[nxt][u]  = *(const float4*)(qss + (l0+u)*D + dq);
          kbf[nxt][u] = *(const double2*)(kvs + (dq+u)*D + m0);
        }
      }
      #pragma unroll
      for(int du=0;du<4;du++){
        ull k0=(ull)__double_as_longlong(kbf[cur][du].x);
        ull k1=(ull)__double_as_longlong(kbf[cur][du].y);
        #pragma unroll
        for(int ll=0;ll<4;ll++){
          float qv = f4get(qb[cur][ll], du);
          ull q2 = pack2(qv,qv);
          fma2(acc[ll*2],   q2, k0);
          fma2(acc[ll*2+1], q2, k1);
        }
      }
    }
  }
  float* op = OUT + (size_t)(p>>3)*LHD + (size_t)(c*C)*HD + (size_t)(p&7)*D;
  #pragma unroll
  for(int ll=0;ll<4;ll++){
    float sa = sa_s[l0+ll];
    float2 a0=unpack2(acc[ll*2]), a1=unpack2(acc[ll*2+1]);
    *(float4*)(op + (size_t)(l0+ll)*HD + m0) =
      make_float4(a0.x*sa, a0.y*sa, a1.x*sa, a1.y*sa);
  }
}

// ---------------- launch ----------------
extern "C" void kernel_launch(void* const* d_in, const int* in_sizes, int n_in,
                              void* d_out, int out_size){
  const float* Q = (const float*)d_in[0];
  const float* K = (const float*)d_in[1];
  const float* V = (const float*)d_in[2];
  float* OUT = (float*)d_out;

  const int SM_3T  = 3*C*SDT*sizeof(float);   // 52224
  const int SM_OUT = 4*C*D*sizeof(float);     // 65536
  cudaFuncSetAttribute(k_siso,      cudaFuncAttributeMaxDynamicSharedMemorySize, SM_3T);
  cudaFuncSetAttribute(k_conserved, cudaFuncAttributeMaxDynamicSharedMemorySize, SM_3T);
  cudaFuncSetAttribute(k_out,       cudaFuncAttributeMaxDynamicSharedMemorySize, SM_OUT);

  dim3 gpc(NC, P);
  k_prep<<<gpc, 256>>>(Q, K);
  k_siso<<<gpc, 256, SM_3T>>>();
  k_conserved<<<gpc, 256, SM_3T>>>();
  k_vkv<<<gpc, 256>>>(V);
  k_scan_kv<<<dim3(4, P), 256>>>();
  k_out<<<gpc, 256, SM_OUT>>>(OUT, V);
}